// round 5
// baseline (speedup 1.0000x reference)
#include <cuda_runtime.h>
#include <cuda_bf16.h>
#include <cstdint>

// Grid_nd_sample: bilinear interpolation gather, ILP=2, occ=5 blocks/SM.
// in_tensor: (B=16, H=128, W=128, C=256) fp32
// indices:   (B=16, P=8192, 2) fp32  -- coord0 = H axis, coord1 = W axis
// out:       (B, P, C) fp32
//
// One warp = one point. Lane l handles float4 chunks l and l+32 (two 512B
// coalesced segments per gathered row). 8 independent LDG.128 per thread.
// DRAM read traffic is compulsory (~208MB) — the optimization target is
// achieved bandwidth via outstanding-load count (occ * ILP).

static constexpr int B = 16;
static constexpr int H = 128;
static constexpr int W = 128;
static constexpr int C = 256;
static constexpr int P = 8192;
static constexpr int CHUNKS = C / 4;                       // 64 float4 per row
static constexpr long long TOTAL_T = (long long)B * P * 32; // 4,194,304 threads

__device__ __forceinline__ float4 bilerp4(float4 p1, float4 p2, float4 p3, float4 p4,
                                          float mh, float mw)
{
    float4 o;
    float a, c;
    a = fmaf(mh, p2.x - p1.x, p1.x); c = fmaf(mh, p4.x - p3.x, p3.x); o.x = fmaf(mw, c - a, a);
    a = fmaf(mh, p2.y - p1.y, p1.y); c = fmaf(mh, p4.y - p3.y, p3.y); o.y = fmaf(mw, c - a, a);
    a = fmaf(mh, p2.z - p1.z, p1.z); c = fmaf(mh, p4.z - p3.z, p3.z); o.z = fmaf(mw, c - a, a);
    a = fmaf(mh, p2.w - p1.w, p1.w); c = fmaf(mh, p4.w - p3.w, p3.w); o.w = fmaf(mw, c - a, a);
    return o;
}

__global__ __launch_bounds__(256, 5)
void grid_nd_sample_kernel(const float* __restrict__ in_tensor,
                           const float2* __restrict__ indices,
                           float4* __restrict__ out)
{
    unsigned int i = blockIdx.x * blockDim.x + threadIdx.x;  // < TOTAL_T
    unsigned int chunk = i & 31;          // first of two chunks (second = +32)
    unsigned int pidx  = i >> 5;          // b*P + p  (uniform across warp)
    unsigned int b     = pidx >> 13;      // P = 8192 = 2^13

    float2 ind = __ldg(&indices[pidx]);   // warp-broadcast

    float fh = floorf(ind.x);
    float fw = floorf(ind.y);
    int h0 = (int)fh;
    int w0 = (int)fw;
    int h1 = (int)ceilf(ind.x);
    int w1 = (int)ceilf(ind.y);
    float mu_h = ind.x - fh;
    float mu_w = ind.y - fw;

    const float4* base = (const float4*)in_tensor;
    unsigned int boff = b * (H * W * CHUNKS);
    unsigned int r00 = boff + (h0 * W + w0) * CHUNKS + chunk;
    unsigned int r10 = boff + (h1 * W + w0) * CHUNKS + chunk;
    unsigned int r01 = boff + (h0 * W + w1) * CHUNKS + chunk;
    unsigned int r11 = boff + (h1 * W + w1) * CHUNKS + chunk;

    // 8 independent 16B loads in flight.
    float4 p1a = __ldg(&base[r00]);
    float4 p2a = __ldg(&base[r10]);
    float4 p3a = __ldg(&base[r01]);
    float4 p4a = __ldg(&base[r11]);
    float4 p1b = __ldg(&base[r00 + 32]);
    float4 p2b = __ldg(&base[r10 + 32]);
    float4 p3b = __ldg(&base[r01 + 32]);
    float4 p4b = __ldg(&base[r11 + 32]);

    float4 oa = bilerp4(p1a, p2a, p3a, p4a, mu_h, mu_w);
    float4 ob = bilerp4(p1b, p2b, p3b, p4b, mu_h, mu_w);

    unsigned int obase = pidx * (unsigned int)CHUNKS + chunk;
    __stcs(&out[obase], oa);        // streaming store: don't pollute L2
    __stcs(&out[obase + 32], ob);
}

extern "C" void kernel_launch(void* const* d_in, const int* in_sizes, int n_in,
                              void* d_out, int out_size)
{
    const float*  in_tensor = (const float*)d_in[0];
    const float2* indices   = (const float2*)d_in[1];
    float4*       out       = (float4*)d_out;

    const int threads = 256;
    const int blocks  = (int)(TOTAL_T / threads);  // 16384
    grid_nd_sample_kernel<<<blocks, threads>>>(in_tensor, indices, out);
}

// round 7
// speedup vs baseline: 1.1328x; 1.1328x over previous
#include <cuda_runtime.h>
#include <cuda_bf16.h>
#include <cstdint>

// Grid_nd_sample: bilinear interpolation gather.
// in_tensor: (B=16, H=128, W=128, C=256) fp32
// indices:   (B=16, P=8192, 2) fp32  -- coord0 = H axis, coord1 = W axis
// out:       (B, P, C) fp32
//
// Structure: each block owns 32 consecutive points. Indices for all 32 points
// are staged into smem by one coalesced 256B load, so per-point index reads
// are 29-cycle LDS instead of a ~600-cycle LDG at the head of every warp's
// life. Each warp then loops over 4 points; per point, lane l gathers float4
// chunks l and l+32 of the 4 neighbor rows (8 independent LDG.128 in flight).
// The unrolled loop lets ptxas overlap next-point loads with current compute.

static constexpr int B = 16;
static constexpr int H = 128;
static constexpr int W = 128;
static constexpr int C = 256;
static constexpr int P = 8192;
static constexpr int CHUNKS = C / 4;              // 64 float4 per pixel row
static constexpr int PTS_PER_BLOCK = 32;          // 8 warps x 4 points
static constexpr int NBLOCKS = B * P / PTS_PER_BLOCK;  // 4096

__device__ __forceinline__ float4 bilerp4(float4 p1, float4 p2, float4 p3, float4 p4,
                                          float mh, float mw)
{
    float4 o;
    float a, c;
    a = fmaf(mh, p2.x - p1.x, p1.x); c = fmaf(mh, p4.x - p3.x, p3.x); o.x = fmaf(mw, c - a, a);
    a = fmaf(mh, p2.y - p1.y, p1.y); c = fmaf(mh, p4.y - p3.y, p3.y); o.y = fmaf(mw, c - a, a);
    a = fmaf(mh, p2.z - p1.z, p1.z); c = fmaf(mh, p4.z - p3.z, p3.z); o.z = fmaf(mw, c - a, a);
    a = fmaf(mh, p2.w - p1.w, p1.w); c = fmaf(mh, p4.w - p3.w, p3.w); o.w = fmaf(mw, c - a, a);
    return o;
}

__global__ __launch_bounds__(256, 4)
void grid_nd_sample_kernel(const float* __restrict__ in_tensor,
                           const float2* __restrict__ indices,
                           float4* __restrict__ out)
{
    __shared__ float2 sidx[PTS_PER_BLOCK];

    unsigned int tid  = threadIdx.x;
    unsigned int wid  = tid >> 5;           // warp 0..7
    unsigned int lane = tid & 31;
    unsigned int pbase = blockIdx.x * PTS_PER_BLOCK;   // first global point

    // Stage the block's 32 indices (256B, one coalesced transaction).
    if (tid < PTS_PER_BLOCK)
        sidx[tid] = __ldg(&indices[pbase + tid]);
    __syncthreads();

    const float4* base = (const float4*)in_tensor;

#pragma unroll
    for (int j = 0; j < 4; ++j) {
        unsigned int lp   = wid * 4 + j;          // local point 0..31
        unsigned int pidx = pbase + lp;           // global b*P + p
        unsigned int b    = pidx >> 13;           // P = 8192 = 2^13

        float2 ind = sidx[lp];                    // LDS broadcast

        float fh = floorf(ind.x);
        float fw = floorf(ind.y);
        int h0 = (int)fh;
        int w0 = (int)fw;
        int h1 = (int)ceilf(ind.x);
        int w1 = (int)ceilf(ind.y);
        float mu_h = ind.x - fh;
        float mu_w = ind.y - fw;

        unsigned int boff = b * (H * W * CHUNKS);
        unsigned int r00 = boff + (h0 * W + w0) * CHUNKS + lane;
        unsigned int r10 = boff + (h1 * W + w0) * CHUNKS + lane;
        unsigned int r01 = boff + (h0 * W + w1) * CHUNKS + lane;
        unsigned int r11 = boff + (h1 * W + w1) * CHUNKS + lane;

        // 8 independent 16B gathers in flight per thread.
        float4 p1a = __ldg(&base[r00]);
        float4 p2a = __ldg(&base[r10]);
        float4 p3a = __ldg(&base[r01]);
        float4 p4a = __ldg(&base[r11]);
        float4 p1b = __ldg(&base[r00 + 32]);
        float4 p2b = __ldg(&base[r10 + 32]);
        float4 p3b = __ldg(&base[r01 + 32]);
        float4 p4b = __ldg(&base[r11 + 32]);

        float4 oa = bilerp4(p1a, p2a, p3a, p4a, mu_h, mu_w);
        float4 ob = bilerp4(p1b, p2b, p3b, p4b, mu_h, mu_w);

        unsigned int obase = pidx * (unsigned int)CHUNKS + lane;
        __stcs(&out[obase], oa);          // streaming store
        __stcs(&out[obase + 32], ob);
    }
}

extern "C" void kernel_launch(void* const* d_in, const int* in_sizes, int n_in,
                              void* d_out, int out_size)
{
    const float*  in_tensor = (const float*)d_in[0];
    const float2* indices   = (const float2*)d_in[1];
    float4*       out       = (float4*)d_out;

    grid_nd_sample_kernel<<<NBLOCKS, 256>>>(in_tensor, indices, out);
}

// round 9
// speedup vs baseline: 1.1476x; 1.0131x over previous
#include <cuda_runtime.h>
#include <cuda_bf16.h>
#include <cstdint>

// Grid_nd_sample: bilinear interpolation gather — cp.async pipelined version.
// in_tensor: (B=16, H=128, W=128, C=256) fp32
// indices:   (B=16, P=8192, 2) fp32  -- coord0 = H axis, coord1 = W axis
// out:       (B, P, C) fp32
//
// Gather payload lives in SMEM (cp.async.cg), not registers, so MLP no longer
// costs occupancy. 8 warps/block, 2 warps per point (half the C dim each),
// 4 points per pipeline stage, double-buffered: 32KB smem, ~40 regs ->
// 6 blocks/SM, ~48 warps x 8 outstanding 16B gathers = ~384 reqs/SM in flight.
// Per-lane smem data is lane-private -> no __syncthreads in the main loop.

static constexpr int B = 16;
static constexpr int H = 128;
static constexpr int W = 128;
static constexpr int C = 256;
static constexpr int P = 8192;
static constexpr int CHUNKS = C / 4;               // 64 float4 per pixel row
static constexpr int ITERS = 8;                    // pipeline iterations
static constexpr int PPB   = ITERS * 4;            // 32 points per block
static constexpr int NBLOCKS = B * P / PPB;        // 4096

__device__ __forceinline__ void cp16(uint32_t dst_smem, const void* src_gmem) {
    asm volatile("cp.async.cg.shared.global [%0], [%1], 16;"
                 :: "r"(dst_smem), "l"(src_gmem));
}
#define CP_COMMIT() asm volatile("cp.async.commit_group;" ::: "memory")
#define CP_WAIT1()  asm volatile("cp.async.wait_group 1;" ::: "memory")
#define CP_WAIT0()  asm volatile("cp.async.wait_group 0;" ::: "memory")

__global__ __launch_bounds__(256, 6)
void grid_nd_sample_kernel(const float* __restrict__ in_tensor,
                           const float2* __restrict__ indices,
                           float4* __restrict__ out)
{
    // [stage][point-in-iter][row][chunk] : 2*4*4*64*16B = 32KB
    __shared__ float4 buf[2][4][4][CHUNKS];
    __shared__ float2 sidx[PPB];

    const unsigned tid   = threadIdx.x;
    const unsigned wid   = tid >> 5;
    const unsigned lane  = tid & 31;
    const unsigned pt4   = wid >> 1;          // point slot 0..3 within a stage
    const unsigned hf    = wid & 1;           // which half of C this warp owns
    const unsigned chunk = hf * 32 + lane;    // float4 chunk 0..63
    const unsigned pbase = blockIdx.x * PPB;

    if (tid < PPB)
        sidx[tid] = __ldg(&indices[pbase + tid]);
    __syncthreads();

    const float4* base = (const float4*)in_tensor;

    auto issue = [&](int it) {
        int lp = it * 4 + pt4;
        unsigned pidx = pbase + lp;
        unsigned b = pidx >> 13;              // P = 8192 = 2^13
        float2 ind = sidx[lp];
        int h0 = (int)floorf(ind.x);
        int w0 = (int)floorf(ind.y);
        int h1 = (int)ceilf(ind.x);
        int w1 = (int)ceilf(ind.y);
        unsigned boff = b * (H * W * CHUNKS);
        const float4* s0 = &base[boff + (h0 * W + w0) * CHUNKS + chunk];  // p1
        const float4* s1 = &base[boff + (h1 * W + w0) * CHUNKS + chunk];  // p2
        const float4* s2 = &base[boff + (h0 * W + w1) * CHUNKS + chunk];  // p3
        const float4* s3 = &base[boff + (h1 * W + w1) * CHUNKS + chunk];  // p4
        uint32_t d = (uint32_t)__cvta_generic_to_shared(&buf[it & 1][pt4][0][chunk]);
        const uint32_t ROWB = CHUNKS * 16;    // 1024B per row in buf
        cp16(d + 0 * ROWB, s0);
        cp16(d + 1 * ROWB, s1);
        cp16(d + 2 * ROWB, s2);
        cp16(d + 3 * ROWB, s3);
    };

    // Prologue: fill both stages.
    issue(0); CP_COMMIT();
    issue(1); CP_COMMIT();

#pragma unroll
    for (int it = 0; it < ITERS; ++it) {
        if (it < ITERS - 1) { CP_WAIT1(); } else { CP_WAIT0(); }

        int lp = it * 4 + pt4;
        unsigned pidx = pbase + lp;
        float2 ind = sidx[lp];
        float mu_h = ind.x - floorf(ind.x);
        float mu_w = ind.y - floorf(ind.y);

        float4 p1 = buf[it & 1][pt4][0][chunk];
        float4 p2 = buf[it & 1][pt4][1][chunk];
        float4 p3 = buf[it & 1][pt4][2][chunk];
        float4 p4 = buf[it & 1][pt4][3][chunk];

        float4 o;
        {
            float a = fmaf(mu_h, p2.x - p1.x, p1.x);
            float c = fmaf(mu_h, p4.x - p3.x, p3.x);
            o.x = fmaf(mu_w, c - a, a);
        }
        {
            float a = fmaf(mu_h, p2.y - p1.y, p1.y);
            float c = fmaf(mu_h, p4.y - p3.y, p3.y);
            o.y = fmaf(mu_w, c - a, a);
        }
        {
            float a = fmaf(mu_h, p2.z - p1.z, p1.z);
            float c = fmaf(mu_h, p4.z - p3.z, p3.z);
            o.z = fmaf(mu_w, c - a, a);
        }
        {
            float a = fmaf(mu_h, p2.w - p1.w, p1.w);
            float c = fmaf(mu_h, p4.w - p3.w, p3.w);
            o.w = fmaf(mu_w, c - a, a);
        }

        __stcs(&out[pidx * (unsigned)CHUNKS + chunk], o);

        if (it + 2 < ITERS) { issue(it + 2); CP_COMMIT(); }
    }
}

extern "C" void kernel_launch(void* const* d_in, const int* in_sizes, int n_in,
                              void* d_out, int out_size)
{
    const float*  in_tensor = (const float*)d_in[0];
    const float2* indices   = (const float2*)d_in[1];
    float4*       out       = (float4*)d_out;

    grid_nd_sample_kernel<<<NBLOCKS, 256>>>(in_tensor, indices, out);
}